// round 2
// baseline (speedup 1.0000x reference)
#include <cuda_runtime.h>
#include <cuda_bf16.h>

#define HIDDEN 128
#define MAX_ING 20000
#define MAX_CMP 10000

// Precomputed per-node partial activations (allocation-free: __device__ globals).
// P_ing = x_ing @ W1[:128] + b1 ; P_cmp = x_cmp @ W1[128:].
__device__ float g_P_ing[(size_t)MAX_ING * HIDDEN];
__device__ float g_P_cmp[(size_t)MAX_CMP * HIDDEN];

// ---------------------------------------------------------------------------
// Kernel A: precompute P tables. One block = 32 rows (8 warps x 4 rows/warp).
// W half (128x128 f32 = 64KB) staged in dynamic smem. FMA-pipe bound (~29us
// analytical floor for fp32 CUDA cores) — left unchanged this round.
// ---------------------------------------------------------------------------
extern __shared__ float smemW[];

__global__ void precompute_kernel(const float* __restrict__ xi,
                                  const float* __restrict__ xc,
                                  const float* __restrict__ W1,
                                  const float* __restrict__ b1,
                                  int nIng, int nCmp, int ingBlocks)
{
    const float* X;
    float* P;
    const float* Wsrc;
    int nRows;
    bool ing;
    int bid = blockIdx.x;
    if (bid < ingBlocks) {
        ing = true;  X = xi; P = g_P_ing; Wsrc = W1;                   nRows = nIng;
    } else {
        ing = false; bid -= ingBlocks;
        X = xc; P = g_P_cmp; Wsrc = W1 + HIDDEN * HIDDEN;              nRows = nCmp;
    }

    for (int i = threadIdx.x; i < HIDDEN * HIDDEN; i += blockDim.x)
        smemW[i] = Wsrc[i];
    __syncthreads();

    const int warp = threadIdx.x >> 5;
    const int lane = threadIdx.x & 31;
    const int r0 = bid * 32 + warp * 4;

    float xr[4][4];
#pragma unroll
    for (int ri = 0; ri < 4; ri++) {
        int r = r0 + ri;
#pragma unroll
        for (int c = 0; c < 4; c++)
            xr[ri][c] = (r < nRows) ? X[(size_t)r * HIDDEN + c * 32 + lane] : 0.f;
    }

    float acc[4][4];
#pragma unroll
    for (int ri = 0; ri < 4; ri++)
#pragma unroll
        for (int u = 0; u < 4; u++) acc[ri][u] = 0.f;

#pragma unroll
    for (int c = 0; c < 4; c++) {
#pragma unroll 8
        for (int k0 = 0; k0 < 32; k0++) {
            const int k = c * 32 + k0;
            float w[4];
#pragma unroll
            for (int u = 0; u < 4; u++)
                w[u] = smemW[k * HIDDEN + lane + 32 * u];
#pragma unroll
            for (int ri = 0; ri < 4; ri++) {
                float xk = __shfl_sync(0xffffffffu, xr[ri][c], k0);
#pragma unroll
                for (int u = 0; u < 4; u++)
                    acc[ri][u] = fmaf(xk, w[u], acc[ri][u]);
            }
        }
    }

#pragma unroll
    for (int ri = 0; ri < 4; ri++) {
        int r = r0 + ri;
        if (r < nRows) {
#pragma unroll
            for (int u = 0; u < 4; u++) {
                float v = acc[ri][u];
                if (ing) v += b1[lane + 32 * u];
                P[(size_t)r * HIDDEN + lane + 32 * u] = v;
            }
        }
    }
}

// ---------------------------------------------------------------------------
// Kernel B: 8-lane edge groups, 4 edges per warp concurrently.
// Lane layout: grp = lane>>3 picks the edge, sub = lane&7 picks 16 channels
// (float4 at channel sub*4 + 32*it, it=0..3). Each group's LDG.128 covers a
// contiguous 128B line -> 4 clean wavefronts/instr, zero sector waste.
// Reduction: 3 shfl_xor over 8 lanes serve 4 edges at once.
// ---------------------------------------------------------------------------
__global__ void __launch_bounds__(128)
edge_kernel(const int* __restrict__ eidx,
            const float* __restrict__ W2,
            const float* __restrict__ b2,
            float* __restrict__ out,
            int E, int chunk)
{
    const int gw   = (blockIdx.x * blockDim.x + threadIdx.x) >> 5;
    const int lane = threadIdx.x & 31;
    const int sub  = lane & 7;
    const int grp  = lane >> 3;

    long e0 = (long)gw * chunk;
    long e1 = e0 + chunk;
    if (e1 > E) e1 = E;
    if (e0 >= e1) return;

    // W2 slice for this sub-lane: channels sub*4 + 32*it.
    float4 w2v[4];
#pragma unroll
    for (int it = 0; it < 4; it++)
        w2v[it] = reinterpret_cast<const float4*>(W2)[sub + 8 * it];
    const float b2v = __ldg(b2);

    for (long eb = e0; eb < e1; eb += 32) {
        int myS = 0, myD = 0;
        long ee = eb + lane;
        if (ee < e1) {
            myS = eidx[ee];
            myD = eidx[(long)E + ee];
        }
        const int cnt = (int)((e1 - eb < 32) ? (e1 - eb) : 32);

#pragma unroll 2
        for (int i = 0; i < 8; i++) {
            const int slot = 4 * i + grp;          // edge slot within this 32-batch
            const bool valid = slot < cnt;
            int s = __shfl_sync(0xffffffffu, myS, slot);
            int d = __shfl_sync(0xffffffffu, myD, slot);
            if (!valid) { s = 0; d = 0; }          // keep loads in-bounds

            const float4* Pa = reinterpret_cast<const float4*>(g_P_ing + (size_t)s * HIDDEN);
            const float4* Pc = reinterpret_cast<const float4*>(g_P_cmp + (size_t)d * HIDDEN);

            float t = 0.f;
#pragma unroll
            for (int it = 0; it < 4; it++) {
                float4 a = Pa[sub + 8 * it];
                float4 c = Pc[sub + 8 * it];
                float v0 = fmaxf(a.x + c.x, 0.f);
                float v1 = fmaxf(a.y + c.y, 0.f);
                float v2 = fmaxf(a.z + c.z, 0.f);
                float v3 = fmaxf(a.w + c.w, 0.f);
                t = fmaf(v0, w2v[it].x, t);
                t = fmaf(v1, w2v[it].y, t);
                t = fmaf(v2, w2v[it].z, t);
                t = fmaf(v3, w2v[it].w, t);
            }

            // 8-lane reduction (serves all 4 edges at once)
            t += __shfl_xor_sync(0xffffffffu, t, 4);
            t += __shfl_xor_sync(0xffffffffu, t, 2);
            t += __shfl_xor_sync(0xffffffffu, t, 1);

            if (sub == 0 && valid)
                out[eb + slot] = 1.f / (1.f + __expf(-(t + b2v)));
        }
    }
}

// ---------------------------------------------------------------------------
// Launch: precompute -> edge kernel, same stream, graph-capturable.
// ---------------------------------------------------------------------------
extern "C" void kernel_launch(void* const* d_in, const int* in_sizes, int n_in,
                              void* d_out, int out_size)
{
    const float* xi = (const float*)d_in[0];
    const float* xc = (const float*)d_in[1];
    const int*   ei = (const int*)d_in[2];
    const float* W1 = (const float*)d_in[3];
    const float* b1 = (const float*)d_in[4];
    const float* W2 = (const float*)d_in[5];
    const float* b2 = (const float*)d_in[6];
    float* out = (float*)d_out;

    const int nIng = in_sizes[0] / HIDDEN;
    const int nCmp = in_sizes[1] / HIDDEN;
    const int E    = in_sizes[2] / 2;

    const int ingBlocks = (nIng + 31) / 32;
    const int cmpBlocks = (nCmp + 31) / 32;

    const int smemBytes = HIDDEN * HIDDEN * (int)sizeof(float);  // 64 KB
    cudaFuncSetAttribute(precompute_kernel,
                         cudaFuncAttributeMaxDynamicSharedMemorySize, smemBytes);

    precompute_kernel<<<ingBlocks + cmpBlocks, 256, smemBytes>>>(
        xi, xc, W1, b1, nIng, nCmp, ingBlocks);

    const int blocks = 2368;                 // 128-thread CTAs, 16/SM worth
    const int warps  = blocks * (128 / 32);
    const int chunk  = (E + warps - 1) / warps;
    edge_kernel<<<blocks, 128>>>(ei, W2, b2, out, E, chunk);
}

// round 3
// speedup vs baseline: 1.5764x; 1.5764x over previous
#include <cuda_runtime.h>
#include <cuda_bf16.h>

#define HIDDEN 128
#define MAX_ING 20000
#define MAX_CMP 10000

// Precomputed per-node partial activations, stored bf16 (halves L2 gather bytes;
// tables total 7.7MB -> fully L2-resident). P_ing = x_ing@W1[:128] + b1 (bias
// folded here); P_cmp = x_cmp@W1[128:].
__device__ __nv_bfloat16 g_Pb_ing[(size_t)MAX_ING * HIDDEN];
__device__ __nv_bfloat16 g_Pb_cmp[(size_t)MAX_CMP * HIDDEN];

// ---------------------------------------------------------------------------
// Kernel A: precompute P tables in fp32, store bf16.
// One block = 32 rows (8 warps x 4 rows/warp); W half (64KB) in dynamic smem.
// ---------------------------------------------------------------------------
extern __shared__ float smemW[];

__global__ void precompute_kernel(const float* __restrict__ xi,
                                  const float* __restrict__ xc,
                                  const float* __restrict__ W1,
                                  const float* __restrict__ b1,
                                  int nIng, int nCmp, int ingBlocks)
{
    const float* X;
    __nv_bfloat16* P;
    const float* Wsrc;
    int nRows;
    bool ing;
    int bid = blockIdx.x;
    if (bid < ingBlocks) {
        ing = true;  X = xi; P = g_Pb_ing; Wsrc = W1;                  nRows = nIng;
    } else {
        ing = false; bid -= ingBlocks;
        X = xc; P = g_Pb_cmp; Wsrc = W1 + HIDDEN * HIDDEN;             nRows = nCmp;
    }

    for (int i = threadIdx.x; i < HIDDEN * HIDDEN; i += blockDim.x)
        smemW[i] = Wsrc[i];
    __syncthreads();

    const int warp = threadIdx.x >> 5;
    const int lane = threadIdx.x & 31;
    const int r0 = bid * 32 + warp * 4;

    float xr[4][4];
#pragma unroll
    for (int ri = 0; ri < 4; ri++) {
        int r = r0 + ri;
#pragma unroll
        for (int c = 0; c < 4; c++)
            xr[ri][c] = (r < nRows) ? X[(size_t)r * HIDDEN + c * 32 + lane] : 0.f;
    }

    float acc[4][4];
#pragma unroll
    for (int ri = 0; ri < 4; ri++)
#pragma unroll
        for (int u = 0; u < 4; u++) acc[ri][u] = 0.f;

#pragma unroll
    for (int c = 0; c < 4; c++) {
#pragma unroll 8
        for (int k0 = 0; k0 < 32; k0++) {
            const int k = c * 32 + k0;
            float w[4];
#pragma unroll
            for (int u = 0; u < 4; u++)
                w[u] = smemW[k * HIDDEN + lane + 32 * u];
#pragma unroll
            for (int ri = 0; ri < 4; ri++) {
                float xk = __shfl_sync(0xffffffffu, xr[ri][c], k0);
#pragma unroll
                for (int u = 0; u < 4; u++)
                    acc[ri][u] = fmaf(xk, w[u], acc[ri][u]);
            }
        }
    }

#pragma unroll
    for (int ri = 0; ri < 4; ri++) {
        int r = r0 + ri;
        if (r < nRows) {
#pragma unroll
            for (int u = 0; u < 4; u++) {
                float v = acc[ri][u];
                if (ing) v += b1[lane + 32 * u];
                P[(size_t)r * HIDDEN + lane + 32 * u] = __float2bfloat16(v);
            }
        }
    }
}

// ---------------------------------------------------------------------------
// Kernel B: 8-lane edge groups, 4 edges/warp concurrently, bf16 gathers.
// Lane sub (=lane&7) covers channels [sub*16, sub*16+16) as two uint4 loads
// (8 bf16 each); a group's loads span a contiguous 256B row. Per-4-edges warp
// cost: 4 LDG.128 + ~44 hadd2/hmax2/cvt/ffma + 3 shfl -> L2-bytes bound at
// 512B/edge (was 1024B).
// ---------------------------------------------------------------------------
__global__ void __launch_bounds__(128)
edge_kernel(const int* __restrict__ eidx,
            const float* __restrict__ W2,
            const float* __restrict__ b2,
            float* __restrict__ out,
            int E, int chunk)
{
    const int gw   = (blockIdx.x * blockDim.x + threadIdx.x) >> 5;
    const int lane = threadIdx.x & 31;
    const int sub  = lane & 7;
    const int grp  = lane >> 3;

    long e0 = (long)gw * chunk;
    long e1 = e0 + chunk;
    if (e1 > E) e1 = E;
    if (e0 >= e1) return;

    // W2 channels for this sub-lane: [sub*16, sub*16+16).
    float w2r[16];
#pragma unroll
    for (int j = 0; j < 4; j++) {
        float4 v = reinterpret_cast<const float4*>(W2)[sub * 4 + j];
        w2r[j * 4 + 0] = v.x; w2r[j * 4 + 1] = v.y;
        w2r[j * 4 + 2] = v.z; w2r[j * 4 + 3] = v.w;
    }
    const float b2v = __ldg(b2);
    const __nv_bfloat162 zero2 = __float2bfloat162_rn(0.f);

    const uint4* Pi = reinterpret_cast<const uint4*>(g_Pb_ing);
    const uint4* Pc = reinterpret_cast<const uint4*>(g_Pb_cmp);
    const int ROWV = HIDDEN / 8;   // uint4 per row = 16

    for (long eb = e0; eb < e1; eb += 32) {
        int myS = 0, myD = 0;
        long ee = eb + lane;
        if (ee < e1) {
            myS = eidx[ee];
            myD = eidx[(long)E + ee];
        }
        const int cnt = (int)((e1 - eb < 32) ? (e1 - eb) : 32);

#pragma unroll 2
        for (int i = 0; i < 8; i++) {
            const int slot = 4 * i + grp;
            const bool valid = slot < cnt;
            int s = __shfl_sync(0xffffffffu, myS, slot);
            int d = __shfl_sync(0xffffffffu, myD, slot);
            if (!valid) { s = 0; d = 0; }

            const uint4* pa = Pi + (size_t)s * ROWV + sub * 2;
            const uint4* pc = Pc + (size_t)d * ROWV + sub * 2;

            float t = 0.f;
#pragma unroll
            for (int q = 0; q < 2; q++) {
                uint4 ua = pa[q];
                uint4 uc = pc[q];
                const __nv_bfloat162* ha = reinterpret_cast<const __nv_bfloat162*>(&ua);
                const __nv_bfloat162* hc = reinterpret_cast<const __nv_bfloat162*>(&uc);
#pragma unroll
                for (int k = 0; k < 4; k++) {
                    __nv_bfloat162 v = __hmax2(__hadd2(ha[k], hc[k]), zero2);
                    float2 f = __bfloat1622float2(v);
                    t = fmaf(f.x, w2r[q * 8 + k * 2 + 0], t);
                    t = fmaf(f.y, w2r[q * 8 + k * 2 + 1], t);
                }
            }

            // 8-lane reduction (serves 4 edges at once)
            t += __shfl_xor_sync(0xffffffffu, t, 4);
            t += __shfl_xor_sync(0xffffffffu, t, 2);
            t += __shfl_xor_sync(0xffffffffu, t, 1);

            if (sub == 0 && valid)
                out[eb + slot] = 1.f / (1.f + __expf(-(t + b2v)));
        }
    }
}

// ---------------------------------------------------------------------------
// Launch: precompute -> edge kernel, same stream, graph-capturable.
// ---------------------------------------------------------------------------
extern "C" void kernel_launch(void* const* d_in, const int* in_sizes, int n_in,
                              void* d_out, int out_size)
{
    const float* xi = (const float*)d_in[0];
    const float* xc = (const float*)d_in[1];
    const int*   ei = (const int*)d_in[2];
    const float* W1 = (const float*)d_in[3];
    const float* b1 = (const float*)d_in[4];
    const float* W2 = (const float*)d_in[5];
    const float* b2 = (const float*)d_in[6];
    float* out = (float*)d_out;

    const int nIng = in_sizes[0] / HIDDEN;
    const int nCmp = in_sizes[1] / HIDDEN;
    const int E    = in_sizes[2] / 2;

    const int ingBlocks = (nIng + 31) / 32;
    const int cmpBlocks = (nCmp + 31) / 32;

    const int smemBytes = HIDDEN * HIDDEN * (int)sizeof(float);  // 64 KB
    cudaFuncSetAttribute(precompute_kernel,
                         cudaFuncAttributeMaxDynamicSharedMemorySize, smemBytes);

    precompute_kernel<<<ingBlocks + cmpBlocks, 256, smemBytes>>>(
        xi, xc, W1, b1, nIng, nCmp, ingBlocks);

    const int blocks = 2368;
    const int warps  = blocks * (128 / 32);
    const int chunk  = (E + warps - 1) / warps;
    edge_kernel<<<blocks, 128>>>(ei, W2, b2, out, E, chunk);
}

// round 4
// speedup vs baseline: 2.1627x; 1.3719x over previous
#include <cuda_runtime.h>
#include <cuda_bf16.h>
#include <cstdint>

#define HIDDEN 128
#define MAX_ING 20000
#define MAX_CMP 10000

// Precomputed per-node partial activations, bf16 (7.7MB total -> L2-resident).
// P_ing = x_ing@W1[:128] + b1 (bias folded); P_cmp = x_cmp@W1[128:].
__device__ __align__(16) __nv_bfloat16 g_Pb_ing[(size_t)MAX_ING * HIDDEN];
__device__ __align__(16) __nv_bfloat16 g_Pb_cmp[(size_t)MAX_CMP * HIDDEN];

__device__ __forceinline__ uint32_t f32_to_tf32(float f) {
    uint32_t u;
    asm("cvt.rna.tf32.f32 %0, %1;" : "=r"(u) : "f"(f));
    return u;
}

// ---------------------------------------------------------------------------
// Kernel A: precompute P via tensor cores (mma.sync m16n8k8 tf32).
// One block = 128 rows (8 warps x 16 rows). W half (128x128) staged in smem
// as tf32 bit patterns. Per warp: 16 k-steps x 16 n-tiles = 256 HMMA.
// tf32 rounding (2^-11) is 4x finer than the bf16 table quantization, so it
// doesn't move final error materially.
// ---------------------------------------------------------------------------
extern __shared__ uint32_t smemWt[];   // 128*128 tf32 = 64KB

__global__ void __launch_bounds__(256)
precompute_mma_kernel(const float* __restrict__ xi,
                      const float* __restrict__ xc,
                      const float* __restrict__ W1,
                      const float* __restrict__ b1,
                      int nIng, int nCmp, int ingBlocks)
{
    const float* X;
    __nv_bfloat16* P;
    const float* Wsrc;
    int nRows;
    bool ing;
    int bid = blockIdx.x;
    if (bid < ingBlocks) {
        ing = true;  X = xi; P = g_Pb_ing; Wsrc = W1;                  nRows = nIng;
    } else {
        ing = false; bid -= ingBlocks;
        X = xc; P = g_Pb_cmp; Wsrc = W1 + HIDDEN * HIDDEN;             nRows = nCmp;
    }

    // Stage W half into smem, converted to tf32 (vectorized).
    for (int i = threadIdx.x; i < HIDDEN * HIDDEN / 4; i += blockDim.x) {
        float4 w = reinterpret_cast<const float4*>(Wsrc)[i];
        uint4 tw;
        tw.x = f32_to_tf32(w.x); tw.y = f32_to_tf32(w.y);
        tw.z = f32_to_tf32(w.z); tw.w = f32_to_tf32(w.w);
        reinterpret_cast<uint4*>(smemWt)[i] = tw;
    }
    __syncthreads();

    const int warp = threadIdx.x >> 5;
    const int lane = threadIdx.x & 31;
    const int g = lane >> 2;     // group id (row within tile)
    const int t = lane & 3;      // thread in group (col/k index)
    const int r0 = bid * 128 + warp * 16;
    if (r0 >= nRows) return;

    const int rA = r0 + g;
    const int rB = r0 + g + 8;
    const bool vA = rA < nRows, vB = rB < nRows;
    const float* xrA = X + (size_t)(vA ? rA : 0) * HIDDEN;
    const float* xrB = X + (size_t)(vB ? rB : 0) * HIDDEN;

    float d[16][4];
#pragma unroll
    for (int n = 0; n < 16; n++)
#pragma unroll
        for (int j = 0; j < 4; j++) d[n][j] = 0.f;

#pragma unroll
    for (int k = 0; k < 16; k++) {
        const int k0 = k * 8;
        // A fragment (16x8 tf32, row-major)
        uint32_t a0 = f32_to_tf32(vA ? xrA[k0 + t]     : 0.f);
        uint32_t a1 = f32_to_tf32(vB ? xrB[k0 + t]     : 0.f);
        uint32_t a2 = f32_to_tf32(vA ? xrA[k0 + t + 4] : 0.f);
        uint32_t a3 = f32_to_tf32(vB ? xrB[k0 + t + 4] : 0.f);
#pragma unroll
        for (int n = 0; n < 16; n++) {
            // B fragment (8x8, col-major): b0 = W[k0+t][n*8+g], b1 = W[k0+t+4][n*8+g]
            uint32_t b0 = smemWt[(k0 + t) * HIDDEN + n * 8 + g];
            uint32_t b1r = smemWt[(k0 + t + 4) * HIDDEN + n * 8 + g];
            asm volatile(
                "mma.sync.aligned.m16n8k8.row.col.f32.tf32.tf32.f32 "
                "{%0,%1,%2,%3}, {%4,%5,%6,%7}, {%8,%9}, {%0,%1,%2,%3};"
                : "+f"(d[n][0]), "+f"(d[n][1]), "+f"(d[n][2]), "+f"(d[n][3])
                : "r"(a0), "r"(a1), "r"(a2), "r"(a3), "r"(b0), "r"(b1r));
        }
    }

#pragma unroll
    for (int n = 0; n < 16; n++) {
        const int c = n * 8 + 2 * t;
        float v0 = d[n][0], v1 = d[n][1], v2 = d[n][2], v3 = d[n][3];
        if (ing) {
            float bb0 = __ldg(b1 + c), bb1 = __ldg(b1 + c + 1);
            v0 += bb0; v1 += bb1; v2 += bb0; v3 += bb1;
        }
        if (vA)
            *reinterpret_cast<__nv_bfloat162*>(&P[(size_t)rA * HIDDEN + c]) =
                __floats2bfloat162_rn(v0, v1);
        if (vB)
            *reinterpret_cast<__nv_bfloat162*>(&P[(size_t)rB * HIDDEN + c]) =
                __floats2bfloat162_rn(v2, v3);
    }
}

// ---------------------------------------------------------------------------
// Kernel B: 8-lane edge groups, 4 edges/warp, bf16 gathers.
// FIXED layout vs R3: lane sub loads uint4 at index q*8+sub, so each group's
// LDG.128 covers one contiguous 128B line (1 wavefront/group, was 2 with the
// old sub*2+q stride-32B pattern). Halves L1tex wavefront work.
// ---------------------------------------------------------------------------
__global__ void __launch_bounds__(128)
edge_kernel(const int* __restrict__ eidx,
            const float* __restrict__ W2,
            const float* __restrict__ b2,
            float* __restrict__ out,
            int E, int chunk)
{
    const int gw   = (blockIdx.x * blockDim.x + threadIdx.x) >> 5;
    const int lane = threadIdx.x & 31;
    const int sub  = lane & 7;
    const int grp  = lane >> 3;

    long e0 = (long)gw * chunk;
    long e1 = e0 + chunk;
    if (e1 > E) e1 = E;
    if (e0 >= e1) return;

    // W2 channels for this lane: chunk q covers channels (q*8+sub)*8 .. +7.
    float w2q[2][8];
#pragma unroll
    for (int q = 0; q < 2; q++) {
        const int base = (q * 8 + sub) * 8;
#pragma unroll
        for (int j = 0; j < 8; j += 4) {
            float4 v = *reinterpret_cast<const float4*>(W2 + base + j);
            w2q[q][j + 0] = v.x; w2q[q][j + 1] = v.y;
            w2q[q][j + 2] = v.z; w2q[q][j + 3] = v.w;
        }
    }
    const float b2v = __ldg(b2);
    const __nv_bfloat162 zero2 = __float2bfloat162_rn(0.f);

    const uint4* Pi = reinterpret_cast<const uint4*>(g_Pb_ing);
    const uint4* Pc = reinterpret_cast<const uint4*>(g_Pb_cmp);
    const int ROWV = HIDDEN / 8;   // uint4 per row = 16

    for (long eb = e0; eb < e1; eb += 32) {
        int myS = 0, myD = 0;
        long ee = eb + lane;
        if (ee < e1) {
            myS = eidx[ee];
            myD = eidx[(long)E + ee];
        }
        const int cnt = (int)((e1 - eb < 32) ? (e1 - eb) : 32);

#pragma unroll 2
        for (int i = 0; i < 8; i++) {
            const int slot = 4 * i + grp;
            const bool valid = slot < cnt;
            int s = __shfl_sync(0xffffffffu, myS, slot);
            int d = __shfl_sync(0xffffffffu, myD, slot);
            if (!valid) { s = 0; d = 0; }

            const uint4* pa = Pi + (size_t)s * ROWV + sub;
            const uint4* pc = Pc + (size_t)d * ROWV + sub;

            float t = 0.f;
#pragma unroll
            for (int q = 0; q < 2; q++) {
                uint4 ua = pa[q * 8];
                uint4 uc = pc[q * 8];
                const __nv_bfloat162* ha = reinterpret_cast<const __nv_bfloat162*>(&ua);
                const __nv_bfloat162* hc = reinterpret_cast<const __nv_bfloat162*>(&uc);
#pragma unroll
                for (int k = 0; k < 4; k++) {
                    __nv_bfloat162 v = __hmax2(__hadd2(ha[k], hc[k]), zero2);
                    float2 f = __bfloat1622float2(v);
                    t = fmaf(f.x, w2q[q][2 * k + 0], t);
                    t = fmaf(f.y, w2q[q][2 * k + 1], t);
                }
            }

            t += __shfl_xor_sync(0xffffffffu, t, 4);
            t += __shfl_xor_sync(0xffffffffu, t, 2);
            t += __shfl_xor_sync(0xffffffffu, t, 1);

            if (sub == 0 && valid)
                out[eb + slot] = 1.f / (1.f + __expf(-(t + b2v)));
        }
    }
}

// ---------------------------------------------------------------------------
// Launch: precompute (tensor-core) -> edge kernel, graph-capturable.
// ---------------------------------------------------------------------------
extern "C" void kernel_launch(void* const* d_in, const int* in_sizes, int n_in,
                              void* d_out, int out_size)
{
    const float* xi = (const float*)d_in[0];
    const float* xc = (const float*)d_in[1];
    const int*   ei = (const int*)d_in[2];
    const float* W1 = (const float*)d_in[3];
    const float* b1 = (const float*)d_in[4];
    const float* W2 = (const float*)d_in[5];
    const float* b2 = (const float*)d_in[6];
    float* out = (float*)d_out;

    const int nIng = in_sizes[0] / HIDDEN;
    const int nCmp = in_sizes[1] / HIDDEN;
    const int E    = in_sizes[2] / 2;

    const int ingBlocks = (nIng + 127) / 128;
    const int cmpBlocks = (nCmp + 127) / 128;

    const int smemBytes = HIDDEN * HIDDEN * (int)sizeof(uint32_t);  // 64 KB
    cudaFuncSetAttribute(precompute_mma_kernel,
                         cudaFuncAttributeMaxDynamicSharedMemorySize, smemBytes);

    precompute_mma_kernel<<<ingBlocks + cmpBlocks, 256, smemBytes>>>(
        xi, xc, W1, b1, nIng, nCmp, ingBlocks);

    const int blocks = 2368;
    const int warps  = blocks * (128 / 32);
    const int chunk  = (E + warps - 1) / warps;
    edge_kernel<<<blocks, 128>>>(ei, W2, b2, out, E, chunk);
}

// round 5
// speedup vs baseline: 2.2757x; 1.0522x over previous
#include <cuda_runtime.h>
#include <cuda_bf16.h>
#include <cstdint>

#define HIDDEN 128
#define MAX_ING 20000
#define MAX_CMP 10000

// Precomputed per-node partial activations, bf16 (7.7MB total -> L2-resident).
__device__ __align__(16) __nv_bfloat16 g_Pb_ing[(size_t)MAX_ING * HIDDEN];
__device__ __align__(16) __nv_bfloat16 g_Pb_cmp[(size_t)MAX_CMP * HIDDEN];

__device__ __forceinline__ uint32_t f32_to_tf32(float f) {
    uint32_t u;
    asm("cvt.rna.tf32.f32 %0, %1;" : "=r"(u) : "f"(f));
    return u;
}

// packed fp32x2 fma (Blackwell; not emitted by ptxas from C++)
__device__ __forceinline__ unsigned long long fma_f32x2(
    unsigned long long a, unsigned long long b, unsigned long long c) {
    unsigned long long r;
    asm("fma.rn.f32x2 %0, %1, %2, %3;" : "=l"(r) : "l"(a), "l"(b), "l"(c));
    return r;
}

// ---------------------------------------------------------------------------
// Kernel A: precompute P via mma.sync m16n8k8 tf32.
// Block = 128 rows x 64 cols (half of N) -> 32KB smem staging, grid 3.2 waves
// (was 1.6 with full-N blocks). 8 warps x 16 rows; 8 n-tiles x 16 k-steps.
// ---------------------------------------------------------------------------
extern __shared__ uint32_t smemWt[];   // 128*64 tf32 = 32KB

__global__ void __launch_bounds__(256)
precompute_mma_kernel(const float* __restrict__ xi,
                      const float* __restrict__ xc,
                      const float* __restrict__ W1,
                      const float* __restrict__ b1,
                      int nIng, int nCmp, int ingBlocks)
{
    int bid = blockIdx.x;
    const int colOff = (bid & 1) * 64;
    bid >>= 1;

    const float* X;
    __nv_bfloat16* P;
    const float* Wsrc;
    int nRows;
    bool ing;
    if (bid < ingBlocks) {
        ing = true;  X = xi; P = g_Pb_ing; Wsrc = W1;                  nRows = nIng;
    } else {
        ing = false; bid -= ingBlocks;
        X = xc; P = g_Pb_cmp; Wsrc = W1 + HIDDEN * HIDDEN;             nRows = nCmp;
    }

    // Stage W[k][colOff..colOff+64) into smem as tf32 (vec4).
    for (int i = threadIdx.x; i < HIDDEN * 64 / 4; i += blockDim.x) {
        const int k  = i >> 4;          // 16 float4 per 64-col row
        const int jj = (i & 15) * 4;
        float4 w = *reinterpret_cast<const float4*>(Wsrc + k * HIDDEN + colOff + jj);
        uint4 tw;
        tw.x = f32_to_tf32(w.x); tw.y = f32_to_tf32(w.y);
        tw.z = f32_to_tf32(w.z); tw.w = f32_to_tf32(w.w);
        *reinterpret_cast<uint4*>(&smemWt[k * 64 + jj]) = tw;
    }
    __syncthreads();

    const int warp = threadIdx.x >> 5;
    const int lane = threadIdx.x & 31;
    const int g = lane >> 2;
    const int t = lane & 3;
    const int r0 = bid * 128 + warp * 16;
    if (r0 >= nRows) return;

    const int rA = r0 + g;
    const int rB = r0 + g + 8;
    const bool vA = rA < nRows, vB = rB < nRows;
    const float* xrA = X + (size_t)(vA ? rA : 0) * HIDDEN;
    const float* xrB = X + (size_t)(vB ? rB : 0) * HIDDEN;

    float d[8][4];
#pragma unroll
    for (int n = 0; n < 8; n++)
#pragma unroll
        for (int j = 0; j < 4; j++) d[n][j] = 0.f;

#pragma unroll
    for (int k = 0; k < 16; k++) {
        const int k0 = k * 8;
        uint32_t a0 = f32_to_tf32(vA ? xrA[k0 + t]     : 0.f);
        uint32_t a1 = f32_to_tf32(vB ? xrB[k0 + t]     : 0.f);
        uint32_t a2 = f32_to_tf32(vA ? xrA[k0 + t + 4] : 0.f);
        uint32_t a3 = f32_to_tf32(vB ? xrB[k0 + t + 4] : 0.f);
#pragma unroll
        for (int n = 0; n < 8; n++) {
            uint32_t b0  = smemWt[(k0 + t) * 64 + n * 8 + g];
            uint32_t b1r = smemWt[(k0 + t + 4) * 64 + n * 8 + g];
            asm volatile(
                "mma.sync.aligned.m16n8k8.row.col.f32.tf32.tf32.f32 "
                "{%0,%1,%2,%3}, {%4,%5,%6,%7}, {%8,%9}, {%0,%1,%2,%3};"
                : "+f"(d[n][0]), "+f"(d[n][1]), "+f"(d[n][2]), "+f"(d[n][3])
                : "r"(a0), "r"(a1), "r"(a2), "r"(a3), "r"(b0), "r"(b1r));
        }
    }

#pragma unroll
    for (int n = 0; n < 8; n++) {
        const int c = colOff + n * 8 + 2 * t;
        float v0 = d[n][0], v1 = d[n][1], v2 = d[n][2], v3 = d[n][3];
        if (ing) {
            float bb0 = __ldg(b1 + c), bb1 = __ldg(b1 + c + 1);
            v0 += bb0; v1 += bb1; v2 += bb0; v3 += bb1;
        }
        if (vA)
            *reinterpret_cast<__nv_bfloat162*>(&P[(size_t)rA * HIDDEN + c]) =
                __floats2bfloat162_rn(v0, v1);
        if (vB)
            *reinterpret_cast<__nv_bfloat162*>(&P[(size_t)rB * HIDDEN + c]) =
                __floats2bfloat162_rn(v2, v3);
    }
}

// ---------------------------------------------------------------------------
// Kernel B: 8-lane edge groups, 4 edges/warp, bf16 gathers.
// v5: tile-strided full-32 batches (no validity predication in main loop;
// E%32 handled by one tail warp) + packed fma.rn.f32x2 for the W2 dot.
// ---------------------------------------------------------------------------
__device__ __forceinline__ float edge_dot(const uint4* __restrict__ pa,
                                          const uint4* __restrict__ pc,
                                          const unsigned long long w2p[2][4],
                                          __nv_bfloat162 zero2)
{
    unsigned long long acc = 0ull;
#pragma unroll
    for (int q = 0; q < 2; q++) {
        uint4 ua = pa[q * 8];
        uint4 uc = pc[q * 8];
        const __nv_bfloat162* ha = reinterpret_cast<const __nv_bfloat162*>(&ua);
        const __nv_bfloat162* hc = reinterpret_cast<const __nv_bfloat162*>(&uc);
#pragma unroll
        for (int k = 0; k < 4; k++) {
            __nv_bfloat162 v = __hmax2(__hadd2(ha[k], hc[k]), zero2);
            uint32_t vb = *reinterpret_cast<uint32_t*>(&v);
            // bf16x2 -> packed f32x2: lo = vb<<16, hi = vb & 0xffff0000
            unsigned long long vp =
                ((unsigned long long)(vb & 0xFFFF0000u) << 32) |
                (unsigned long long)(vb << 16);
            acc = fma_f32x2(vp, w2p[q][k], acc);
        }
    }
    uint32_t alo, ahi;
    asm("mov.b64 {%0,%1}, %2;" : "=r"(alo), "=r"(ahi) : "l"(acc));
    return __uint_as_float(alo) + __uint_as_float(ahi);
}

__global__ void __launch_bounds__(256)
edge_kernel(const int* __restrict__ eidx,
            const float* __restrict__ W2,
            const float* __restrict__ b2,
            float* __restrict__ out,
            int E)
{
    const int totalWarps = gridDim.x * (blockDim.x >> 5);
    const int gw   = blockIdx.x * (blockDim.x >> 5) + (threadIdx.x >> 5);
    const int lane = threadIdx.x & 31;
    const int sub  = lane & 7;
    const int grp  = lane >> 3;

    // W2 pairs for this lane packed as f32x2: chunk q covers chans (q*8+sub)*8..+7
    unsigned long long w2p[2][4];
#pragma unroll
    for (int q = 0; q < 2; q++) {
        const int base = (q * 8 + sub) * 8;
#pragma unroll
        for (int k = 0; k < 4; k++) {
            float lo = W2[base + 2 * k], hi = W2[base + 2 * k + 1];
            unsigned long long p;
            asm("mov.b64 %0, {%1,%2};" : "=l"(p) : "r"(__float_as_uint(lo)), "r"(__float_as_uint(hi)));
            w2p[q][k] = p;
        }
    }
    const float b2v = __ldg(b2);
    const __nv_bfloat162 zero2 = __float2bfloat162_rn(0.f);

    const uint4* Pi = reinterpret_cast<const uint4*>(g_Pb_ing);
    const uint4* Pc = reinterpret_cast<const uint4*>(g_Pb_cmp);
    const int ROWV = HIDDEN / 8;   // 16 uint4 per row

    const int fullTiles = E >> 5;

    for (int tile = gw; tile < fullTiles; tile += totalWarps) {
        const long eb = (long)tile << 5;
        const int myS = eidx[eb + lane];
        const int myD = eidx[(long)E + eb + lane];

#pragma unroll 2
        for (int i = 0; i < 8; i++) {
            const int slot = 4 * i + grp;
            const int s = __shfl_sync(0xffffffffu, myS, slot);
            const int d = __shfl_sync(0xffffffffu, myD, slot);

            float t = edge_dot(Pi + (size_t)s * ROWV + sub,
                               Pc + (size_t)d * ROWV + sub, w2p, zero2);

            t += __shfl_xor_sync(0xffffffffu, t, 4);
            t += __shfl_xor_sync(0xffffffffu, t, 2);
            t += __shfl_xor_sync(0xffffffffu, t, 1);

            if (sub == 0)
                out[eb + slot] = 1.f / (1.f + __expf(-(t + b2v)));
        }
    }

    // Tail (E % 32 edges) — one designated warp, predicated path.
    const int rem = E & 31;
    if (rem && gw == (fullTiles % totalWarps)) {
        const long eb = (long)fullTiles << 5;
        int myS = 0, myD = 0;
        if (eb + lane < E) {
            myS = eidx[eb + lane];
            myD = eidx[(long)E + eb + lane];
        }
#pragma unroll 2
        for (int i = 0; i < 8; i++) {
            const int slot = 4 * i + grp;
            const bool valid = slot < rem;
            int s = __shfl_sync(0xffffffffu, myS, slot);
            int d = __shfl_sync(0xffffffffu, myD, slot);
            if (!valid) { s = 0; d = 0; }

            float t = edge_dot(Pi + (size_t)s * ROWV + sub,
                               Pc + (size_t)d * ROWV + sub, w2p, zero2);

            t += __shfl_xor_sync(0xffffffffu, t, 4);
            t += __shfl_xor_sync(0xffffffffu, t, 2);
            t += __shfl_xor_sync(0xffffffffu, t, 1);

            if (sub == 0 && valid)
                out[eb + slot] = 1.f / (1.f + __expf(-(t + b2v)));
        }
    }
}

// ---------------------------------------------------------------------------
// Launch: precompute (tensor-core) -> edge kernel, graph-capturable.
// ---------------------------------------------------------------------------
extern "C" void kernel_launch(void* const* d_in, const int* in_sizes, int n_in,
                              void* d_out, int out_size)
{
    const float* xi = (const float*)d_in[0];
    const float* xc = (const float*)d_in[1];
    const int*   ei = (const int*)d_in[2];
    const float* W1 = (const float*)d_in[3];
    const float* b1 = (const float*)d_in[4];
    const float* W2 = (const float*)d_in[5];
    const float* b2 = (const float*)d_in[6];
    float* out = (float*)d_out;

    const int nIng = in_sizes[0] / HIDDEN;
    const int nCmp = in_sizes[1] / HIDDEN;
    const int E    = in_sizes[2] / 2;

    const int ingBlocks = (nIng + 127) / 128;
    const int cmpBlocks = (nCmp + 127) / 128;

    const int smemBytes = HIDDEN * 64 * (int)sizeof(uint32_t);  // 32 KB
    cudaFuncSetAttribute(precompute_mma_kernel,
                         cudaFuncAttributeMaxDynamicSharedMemorySize, smemBytes);

    precompute_mma_kernel<<<2 * (ingBlocks + cmpBlocks), 256, smemBytes>>>(
        xi, xc, W1, b1, nIng, nCmp, ingBlocks);

    edge_kernel<<<1184, 256>>>(ei, W2, b2, out, E);
}

// round 6
// speedup vs baseline: 2.6867x; 1.1806x over previous
#include <cuda_runtime.h>
#include <cuda_bf16.h>
#include <cstdint>

#define HIDDEN 128
#define MAX_ING 20000
#define MAX_CMP 10000

// Precomputed per-node partial activations, bf16 (7.7MB total -> L2-resident).
__device__ __align__(16) __nv_bfloat16 g_Pb_ing[(size_t)MAX_ING * HIDDEN];
__device__ __align__(16) __nv_bfloat16 g_Pb_cmp[(size_t)MAX_CMP * HIDDEN];

__device__ __forceinline__ uint32_t f32_to_tf32(float f) {
    uint32_t u;
    asm("cvt.rna.tf32.f32 %0, %1;" : "=r"(u) : "f"(f));
    return u;
}

// packed fp32x2 fma (Blackwell; ptxas never auto-fuses to this)
__device__ __forceinline__ unsigned long long fma_f32x2(
    unsigned long long a, unsigned long long b, unsigned long long c) {
    unsigned long long r;
    asm("fma.rn.f32x2 %0, %1, %2, %3;" : "=l"(r) : "l"(a), "l"(b), "l"(c));
    return r;
}

// ---------------------------------------------------------------------------
// Kernel A: precompute P via mma.sync m16n8k8 tf32.
// Block = 128 rows x 64 cols. smem stride PADDED to 72 words: bank =
// 8t + 8n + g (mod 32) -> conflict-free B-fragment LDS (was 4-way conflicted
// at stride 64, which dominated this kernel's runtime).
// ---------------------------------------------------------------------------
#define WSTRIDE 72
extern __shared__ uint32_t smemWt[];   // 128*72 tf32 = 36.9KB

__global__ void __launch_bounds__(256)
precompute_mma_kernel(const float* __restrict__ xi,
                      const float* __restrict__ xc,
                      const float* __restrict__ W1,
                      const float* __restrict__ b1,
                      int nIng, int nCmp, int ingBlocks)
{
    int bid = blockIdx.x;
    const int colOff = (bid & 1) * 64;
    bid >>= 1;

    const float* X;
    __nv_bfloat16* P;
    const float* Wsrc;
    int nRows;
    bool ing;
    if (bid < ingBlocks) {
        ing = true;  X = xi; P = g_Pb_ing; Wsrc = W1;                  nRows = nIng;
    } else {
        ing = false; bid -= ingBlocks;
        X = xc; P = g_Pb_cmp; Wsrc = W1 + HIDDEN * HIDDEN;             nRows = nCmp;
    }

    // Stage W[k][colOff..colOff+64) into padded smem as tf32 (vec4).
    for (int i = threadIdx.x; i < HIDDEN * 64 / 4; i += blockDim.x) {
        const int k  = i >> 4;          // 16 float4 per 64-col row
        const int jj = (i & 15) * 4;
        float4 w = *reinterpret_cast<const float4*>(Wsrc + k * HIDDEN + colOff + jj);
        uint4 tw;
        tw.x = f32_to_tf32(w.x); tw.y = f32_to_tf32(w.y);
        tw.z = f32_to_tf32(w.z); tw.w = f32_to_tf32(w.w);
        *reinterpret_cast<uint4*>(&smemWt[k * WSTRIDE + jj]) = tw;
    }
    __syncthreads();

    const int warp = threadIdx.x >> 5;
    const int lane = threadIdx.x & 31;
    const int g = lane >> 2;
    const int t = lane & 3;
    const int r0 = bid * 128 + warp * 16;
    if (r0 >= nRows) return;

    const int rA = r0 + g;
    const int rB = r0 + g + 8;
    const bool vA = rA < nRows, vB = rB < nRows;
    const float* xrA = X + (size_t)(vA ? rA : 0) * HIDDEN;
    const float* xrB = X + (size_t)(vB ? rB : 0) * HIDDEN;

    float d[8][4];
#pragma unroll
    for (int n = 0; n < 8; n++)
#pragma unroll
        for (int j = 0; j < 4; j++) d[n][j] = 0.f;

#pragma unroll
    for (int k = 0; k < 16; k++) {
        const int k0 = k * 8;
        uint32_t a0 = f32_to_tf32(vA ? xrA[k0 + t]     : 0.f);
        uint32_t a1 = f32_to_tf32(vB ? xrB[k0 + t]     : 0.f);
        uint32_t a2 = f32_to_tf32(vA ? xrA[k0 + t + 4] : 0.f);
        uint32_t a3 = f32_to_tf32(vB ? xrB[k0 + t + 4] : 0.f);
#pragma unroll
        for (int n = 0; n < 8; n++) {
            uint32_t b0  = smemWt[(k0 + t) * WSTRIDE + n * 8 + g];
            uint32_t b1r = smemWt[(k0 + t + 4) * WSTRIDE + n * 8 + g];
            asm volatile(
                "mma.sync.aligned.m16n8k8.row.col.f32.tf32.tf32.f32 "
                "{%0,%1,%2,%3}, {%4,%5,%6,%7}, {%8,%9}, {%0,%1,%2,%3};"
                : "+f"(d[n][0]), "+f"(d[n][1]), "+f"(d[n][2]), "+f"(d[n][3])
                : "r"(a0), "r"(a1), "r"(a2), "r"(a3), "r"(b0), "r"(b1r));
        }
    }

#pragma unroll
    for (int n = 0; n < 8; n++) {
        const int c = colOff + n * 8 + 2 * t;
        float v0 = d[n][0], v1 = d[n][1], v2 = d[n][2], v3 = d[n][3];
        if (ing) {
            float bb0 = __ldg(b1 + c), bb1 = __ldg(b1 + c + 1);
            v0 += bb0; v1 += bb1; v2 += bb0; v3 += bb1;
        }
        if (vA)
            *reinterpret_cast<__nv_bfloat162*>(&P[(size_t)rA * HIDDEN + c]) =
                __floats2bfloat162_rn(v0, v1);
        if (vB)
            *reinterpret_cast<__nv_bfloat162*>(&P[(size_t)rB * HIDDEN + c]) =
                __floats2bfloat162_rn(v2, v3);
    }
}

// ---------------------------------------------------------------------------
// Kernel B: 8-lane edge groups, 4 edges/warp, bf16 gathers, tile-strided
// full-32 batches, packed fma.rn.f32x2 dot. Unchanged from R5 (38.8us,
// latency/L2 co-limited).
// ---------------------------------------------------------------------------
__device__ __forceinline__ float edge_dot(const uint4* __restrict__ pa,
                                          const uint4* __restrict__ pc,
                                          const unsigned long long w2p[2][4],
                                          __nv_bfloat162 zero2)
{
    unsigned long long acc = 0ull;
#pragma unroll
    for (int q = 0; q < 2; q++) {
        uint4 ua = pa[q * 8];
        uint4 uc = pc[q * 8];
        const __nv_bfloat162* ha = reinterpret_cast<const __nv_bfloat162*>(&ua);
        const __nv_bfloat162* hc = reinterpret_cast<const __nv_bfloat162*>(&uc);
#pragma unroll
        for (int k = 0; k < 4; k++) {
            __nv_bfloat162 v = __hmax2(__hadd2(ha[k], hc[k]), zero2);
            uint32_t vb = *reinterpret_cast<uint32_t*>(&v);
            unsigned long long vp =
                ((unsigned long long)(vb & 0xFFFF0000u) << 32) |
                (unsigned long long)(vb << 16);
            acc = fma_f32x2(vp, w2p[q][k], acc);
        }
    }
    uint32_t alo, ahi;
    asm("mov.b64 {%0,%1}, %2;" : "=r"(alo), "=r"(ahi) : "l"(acc));
    return __uint_as_float(alo) + __uint_as_float(ahi);
}

__global__ void __launch_bounds__(256)
edge_kernel(const int* __restrict__ eidx,
            const float* __restrict__ W2,
            const float* __restrict__ b2,
            float* __restrict__ out,
            int E)
{
    const int totalWarps = gridDim.x * (blockDim.x >> 5);
    const int gw   = blockIdx.x * (blockDim.x >> 5) + (threadIdx.x >> 5);
    const int lane = threadIdx.x & 31;
    const int sub  = lane & 7;
    const int grp  = lane >> 3;

    unsigned long long w2p[2][4];
#pragma unroll
    for (int q = 0; q < 2; q++) {
        const int base = (q * 8 + sub) * 8;
#pragma unroll
        for (int k = 0; k < 4; k++) {
            float lo = W2[base + 2 * k], hi = W2[base + 2 * k + 1];
            unsigned long long p;
            asm("mov.b64 %0, {%1,%2};" : "=l"(p) : "r"(__float_as_uint(lo)), "r"(__float_as_uint(hi)));
            w2p[q][k] = p;
        }
    }
    const float b2v = __ldg(b2);
    const __nv_bfloat162 zero2 = __float2bfloat162_rn(0.f);

    const uint4* Pi = reinterpret_cast<const uint4*>(g_Pb_ing);
    const uint4* Pc = reinterpret_cast<const uint4*>(g_Pb_cmp);
    const int ROWV = HIDDEN / 8;

    const int fullTiles = E >> 5;

    for (int tile = gw; tile < fullTiles; tile += totalWarps) {
        const long eb = (long)tile << 5;
        const int myS = eidx[eb + lane];
        const int myD = eidx[(long)E + eb + lane];

#pragma unroll 2
        for (int i = 0; i < 8; i++) {
            const int slot = 4 * i + grp;
            const int s = __shfl_sync(0xffffffffu, myS, slot);
            const int d = __shfl_sync(0xffffffffu, myD, slot);

            float t = edge_dot(Pi + (size_t)s * ROWV + sub,
                               Pc + (size_t)d * ROWV + sub, w2p, zero2);

            t += __shfl_xor_sync(0xffffffffu, t, 4);
            t += __shfl_xor_sync(0xffffffffu, t, 2);
            t += __shfl_xor_sync(0xffffffffu, t, 1);

            if (sub == 0)
                out[eb + slot] = 1.f / (1.f + __expf(-(t + b2v)));
        }
    }

    const int rem = E & 31;
    if (rem && gw == (fullTiles % totalWarps)) {
        const long eb = (long)fullTiles << 5;
        int myS = 0, myD = 0;
        if (eb + lane < E) {
            myS = eidx[eb + lane];
            myD = eidx[(long)E + eb + lane];
        }
#pragma unroll 2
        for (int i = 0; i < 8; i++) {
            const int slot = 4 * i + grp;
            const bool valid = slot < rem;
            int s = __shfl_sync(0xffffffffu, myS, slot);
            int d = __shfl_sync(0xffffffffu, myD, slot);
            if (!valid) { s = 0; d = 0; }

            float t = edge_dot(Pi + (size_t)s * ROWV + sub,
                               Pc + (size_t)d * ROWV + sub, w2p, zero2);

            t += __shfl_xor_sync(0xffffffffu, t, 4);
            t += __shfl_xor_sync(0xffffffffu, t, 2);
            t += __shfl_xor_sync(0xffffffffu, t, 1);

            if (sub == 0 && valid)
                out[eb + slot] = 1.f / (1.f + __expf(-(t + b2v)));
        }
    }
}

// ---------------------------------------------------------------------------
// Launch: precompute (tensor-core, conflict-free) -> edge kernel.
// ---------------------------------------------------------------------------
extern "C" void kernel_launch(void* const* d_in, const int* in_sizes, int n_in,
                              void* d_out, int out_size)
{
    const float* xi = (const float*)d_in[0];
    const float* xc = (const float*)d_in[1];
    const int*   ei = (const int*)d_in[2];
    const float* W1 = (const float*)d_in[3];
    const float* b1 = (const float*)d_in[4];
    const float* W2 = (const float*)d_in[5];
    const float* b2 = (const float*)d_in[6];
    float* out = (float*)d_out;

    const int nIng = in_sizes[0] / HIDDEN;
    const int nCmp = in_sizes[1] / HIDDEN;
    const int E    = in_sizes[2] / 2;

    const int ingBlocks = (nIng + 127) / 128;
    const int cmpBlocks = (nCmp + 127) / 128;

    const int smemBytes = HIDDEN * WSTRIDE * (int)sizeof(uint32_t);  // 36.9 KB
    cudaFuncSetAttribute(precompute_mma_kernel,
                         cudaFuncAttributeMaxDynamicSharedMemorySize, smemBytes);

    precompute_mma_kernel<<<2 * (ingBlocks + cmpBlocks), 256, smemBytes>>>(
        xi, xc, W1, b1, nIng, nCmp, ingBlocks);

    edge_kernel<<<1184, 256>>>(ei, W2, b2, out, E);
}

// round 7
// speedup vs baseline: 3.1457x; 1.1709x over previous
#include <cuda_runtime.h>
#include <cuda_bf16.h>
#include <cstdint>

#define HIDDEN 128
#define MAX_ING 20000
#define MAX_CMP 10000

// Precomputed per-node partial activations, bf16 (7.7MB total -> L2-resident).
__device__ __align__(16) __nv_bfloat16 g_Pb_ing[(size_t)MAX_ING * HIDDEN];
__device__ __align__(16) __nv_bfloat16 g_Pb_cmp[(size_t)MAX_CMP * HIDDEN];

// packed fp32x2 fma (Blackwell; ptxas never auto-fuses to this)
__device__ __forceinline__ unsigned long long fma_f32x2(
    unsigned long long a, unsigned long long b, unsigned long long c) {
    unsigned long long r;
    asm("fma.rn.f32x2 %0, %1, %2, %3;" : "=l"(r) : "l"(a), "l"(b), "l"(c));
    return r;
}

// pack two f32 -> bf16x2 reg, lo in low half
__device__ __forceinline__ uint32_t pack_bf16x2(float lo, float hi) {
    uint32_t r;
    asm("cvt.rn.bf16x2.f32 %0, %1, %2;" : "=r"(r) : "f"(hi), "f"(lo));
    return r;
}

__device__ __forceinline__ uint32_t smem_u32(const void* p) {
    return (uint32_t)__cvta_generic_to_shared(p);
}

// ---------------------------------------------------------------------------
// Kernel A: precompute P via bf16 mma.sync m16n8k16 + ldmatrix.x2.trans.
// Block = 128 rows x 64 cols. W half staged as bf16, stride 72 (144B/row ->
// +4 banks per row: LDSM conflict-free). Per warp: 8 k-steps x (4 LDG.64 +
// 4 CVT + 8 LDSM.x2 + 8 HMMA.16816) = ~192 issue slots (was ~650 with tf32
// scalar-LDS version).
// ---------------------------------------------------------------------------
#define WS 72   // bf16 elements per smem row
extern __shared__ __nv_bfloat16 smemWb[];   // 128*72*2 = 18432 B

__global__ void __launch_bounds__(256)
precompute_mma_kernel(const float* __restrict__ xi,
                      const float* __restrict__ xc,
                      const float* __restrict__ W1,
                      const float* __restrict__ b1,
                      int nIng, int nCmp, int ingBlocks)
{
    int bid = blockIdx.x;
    const int colOff = (bid & 1) * 64;
    bid >>= 1;

    const float* X;
    __nv_bfloat16* P;
    const float* Wsrc;
    int nRows;
    bool ing;
    if (bid < ingBlocks) {
        ing = true;  X = xi; P = g_Pb_ing; Wsrc = W1;                  nRows = nIng;
    } else {
        ing = false; bid -= ingBlocks;
        X = xc; P = g_Pb_cmp; Wsrc = W1 + HIDDEN * HIDDEN;             nRows = nCmp;
    }

    // Stage W[k][colOff..colOff+64) as bf16 into padded smem.
    for (int i = threadIdx.x; i < HIDDEN * 64 / 4; i += blockDim.x) {
        const int k  = i >> 4;          // 16 float4 per 64-col row
        const int jj = (i & 15) * 4;
        float4 w = *reinterpret_cast<const float4*>(Wsrc + k * HIDDEN + colOff + jj);
        uint2 pw;
        pw.x = pack_bf16x2(w.x, w.y);
        pw.y = pack_bf16x2(w.z, w.w);
        *reinterpret_cast<uint2*>(&smemWb[k * WS + jj]) = pw;
    }
    __syncthreads();

    const int warp = threadIdx.x >> 5;
    const int lane = threadIdx.x & 31;
    const int g = lane >> 2;
    const int t = lane & 3;
    const int r0 = bid * 128 + warp * 16;
    if (r0 >= nRows) return;

    const int rA = r0 + g;
    const int rB = r0 + g + 8;
    const bool vA = rA < nRows, vB = rB < nRows;
    const float* xrA = X + (size_t)(vA ? rA : 0) * HIDDEN;
    const float* xrB = X + (size_t)(vB ? rB : 0) * HIDDEN;

    // ldmatrix row base for this lane (lanes 0-15 address the two 8x8 k-tiles)
    const uint32_t ldsmBase = smem_u32(&smemWb[(lane & 15) * WS]);

    float d[8][4];
#pragma unroll
    for (int n = 0; n < 8; n++)
#pragma unroll
        for (int j = 0; j < 4; j++) d[n][j] = 0.f;

#pragma unroll
    for (int k = 0; k < 8; k++) {
        const int k0 = k * 16;
        // A fragment (16x16 bf16, row-major): two f32 -> one bf16x2 reg each
        float2 fa0 = *reinterpret_cast<const float2*>(xrA + k0 + 2 * t);
        float2 fa1 = *reinterpret_cast<const float2*>(xrB + k0 + 2 * t);
        float2 fa2 = *reinterpret_cast<const float2*>(xrA + k0 + 2 * t + 8);
        float2 fa3 = *reinterpret_cast<const float2*>(xrB + k0 + 2 * t + 8);
        uint32_t a0 = pack_bf16x2(vA ? fa0.x : 0.f, vA ? fa0.y : 0.f);
        uint32_t a1 = pack_bf16x2(vB ? fa1.x : 0.f, vB ? fa1.y : 0.f);
        uint32_t a2 = pack_bf16x2(vA ? fa2.x : 0.f, vA ? fa2.y : 0.f);
        uint32_t a3 = pack_bf16x2(vB ? fa3.x : 0.f, vB ? fa3.y : 0.f);

        const uint32_t kAddr = ldsmBase + k0 * WS * 2;
#pragma unroll
        for (int n = 0; n < 8; n++) {
            uint32_t b0, b1r;
            asm volatile(
                "ldmatrix.sync.aligned.m8n8.x2.trans.shared.b16 {%0,%1}, [%2];"
                : "=r"(b0), "=r"(b1r) : "r"(kAddr + n * 16));
            asm volatile(
                "mma.sync.aligned.m16n8k16.row.col.f32.bf16.bf16.f32 "
                "{%0,%1,%2,%3}, {%4,%5,%6,%7}, {%8,%9}, {%0,%1,%2,%3};"
                : "+f"(d[n][0]), "+f"(d[n][1]), "+f"(d[n][2]), "+f"(d[n][3])
                : "r"(a0), "r"(a1), "r"(a2), "r"(a3), "r"(b0), "r"(b1r));
        }
    }

#pragma unroll
    for (int n = 0; n < 8; n++) {
        const int c = colOff + n * 8 + 2 * t;
        float v0 = d[n][0], v1 = d[n][1], v2 = d[n][2], v3 = d[n][3];
        if (ing) {
            float bb0 = __ldg(b1 + c), bb1 = __ldg(b1 + c + 1);
            v0 += bb0; v1 += bb1; v2 += bb0; v3 += bb1;
        }
        if (vA)
            *reinterpret_cast<__nv_bfloat162*>(&P[(size_t)rA * HIDDEN + c]) =
                __floats2bfloat162_rn(v0, v1);
        if (vB)
            *reinterpret_cast<__nv_bfloat162*>(&P[(size_t)rB * HIDDEN + c]) =
                __floats2bfloat162_rn(v2, v3);
    }
}

// ---------------------------------------------------------------------------
// Kernel B: 8-lane edge groups, 4 edges/warp, bf16 gathers, tile-strided,
// fma.rn.f32x2 dot. At the chip LTS cap (13.2 TB/s) -- unchanged.
// ---------------------------------------------------------------------------
__device__ __forceinline__ float edge_dot(const uint4* __restrict__ pa,
                                          const uint4* __restrict__ pc,
                                          const unsigned long long w2p[2][4],
                                          __nv_bfloat162 zero2)
{
    unsigned long long acc = 0ull;
#pragma unroll
    for (int q = 0; q < 2; q++) {
        uint4 ua = pa[q * 8];
        uint4 uc = pc[q * 8];
        const __nv_bfloat162* ha = reinterpret_cast<const __nv_bfloat162*>(&ua);
        const __nv_bfloat162* hc = reinterpret_cast<const __nv_bfloat162*>(&uc);
#pragma unroll
        for (int k = 0; k < 4; k++) {
            __nv_bfloat162 v = __hmax2(__hadd2(ha[k], hc[k]), zero2);
            uint32_t vb = *reinterpret_cast<uint32_t*>(&v);
            unsigned long long vp =
                ((unsigned long long)(vb & 0xFFFF0000u) << 32) |
                (unsigned long long)(vb << 16);
            acc = fma_f32x2(vp, w2p[q][k], acc);
        }
    }
    uint32_t alo, ahi;
    asm("mov.b64 {%0,%1}, %2;" : "=r"(alo), "=r"(ahi) : "l"(acc));
    return __uint_as_float(alo) + __uint_as_float(ahi);
}

__global__ void __launch_bounds__(256)
edge_kernel(const int* __restrict__ eidx,
            const float* __restrict__ W2,
            const float* __restrict__ b2,
            float* __restrict__ out,
            int E)
{
    const int totalWarps = gridDim.x * (blockDim.x >> 5);
    const int gw   = blockIdx.x * (blockDim.x >> 5) + (threadIdx.x >> 5);
    const int lane = threadIdx.x & 31;
    const int sub  = lane & 7;
    const int grp  = lane >> 3;

    unsigned long long w2p[2][4];
#pragma unroll
    for (int q = 0; q < 2; q++) {
        const int base = (q * 8 + sub) * 8;
#pragma unroll
        for (int k = 0; k < 4; k++) {
            float lo = W2[base + 2 * k], hi = W2[base + 2 * k + 1];
            unsigned long long p;
            asm("mov.b64 %0, {%1,%2};" : "=l"(p) : "r"(__float_as_uint(lo)), "r"(__float_as_uint(hi)));
            w2p[q][k] = p;
        }
    }
    const float b2v = __ldg(b2);
    const __nv_bfloat162 zero2 = __float2bfloat162_rn(0.f);

    const uint4* Pi = reinterpret_cast<const uint4*>(g_Pb_ing);
    const uint4* Pc = reinterpret_cast<const uint4*>(g_Pb_cmp);
    const int ROWV = HIDDEN / 8;

    const int fullTiles = E >> 5;

    for (int tile = gw; tile < fullTiles; tile += totalWarps) {
        const long eb = (long)tile << 5;
        const int myS = eidx[eb + lane];
        const int myD = eidx[(long)E + eb + lane];

#pragma unroll 2
        for (int i = 0; i < 8; i++) {
            const int slot = 4 * i + grp;
            const int s = __shfl_sync(0xffffffffu, myS, slot);
            const int d = __shfl_sync(0xffffffffu, myD, slot);

            float t = edge_dot(Pi + (size_t)s * ROWV + sub,
                               Pc + (size_t)d * ROWV + sub, w2p, zero2);

            t += __shfl_xor_sync(0xffffffffu, t, 4);
            t += __shfl_xor_sync(0xffffffffu, t, 2);
            t += __shfl_xor_sync(0xffffffffu, t, 1);

            if (sub == 0)
                out[eb + slot] = 1.f / (1.f + __expf(-(t + b2v)));
        }
    }

    const int rem = E & 31;
    if (rem && gw == (fullTiles % totalWarps)) {
        const long eb = (long)fullTiles << 5;
        int myS = 0, myD = 0;
        if (eb + lane < E) {
            myS = eidx[eb + lane];
            myD = eidx[(long)E + eb + lane];
        }
#pragma unroll 2
        for (int i = 0; i < 8; i++) {
            const int slot = 4 * i + grp;
            const bool valid = slot < rem;
            int s = __shfl_sync(0xffffffffu, myS, slot);
            int d = __shfl_sync(0xffffffffu, myD, slot);
            if (!valid) { s = 0; d = 0; }

            float t = edge_dot(Pi + (size_t)s * ROWV + sub,
                               Pc + (size_t)d * ROWV + sub, w2p, zero2);

            t += __shfl_xor_sync(0xffffffffu, t, 4);
            t += __shfl_xor_sync(0xffffffffu, t, 2);
            t += __shfl_xor_sync(0xffffffffu, t, 1);

            if (sub == 0 && valid)
                out[eb + slot] = 1.f / (1.f + __expf(-(t + b2v)));
        }
    }
}

// ---------------------------------------------------------------------------
// Launch: precompute (bf16 HMMA + ldmatrix) -> edge kernel.
// ---------------------------------------------------------------------------
extern "C" void kernel_launch(void* const* d_in, const int* in_sizes, int n_in,
                              void* d_out, int out_size)
{
    const float* xi = (const float*)d_in[0];
    const float* xc = (const float*)d_in[1];
    const int*   ei = (const int*)d_in[2];
    const float* W1 = (const float*)d_in[3];
    const float* b1 = (const float*)d_in[4];
    const float* W2 = (const float*)d_in[5];
    const float* b2 = (const float*)d_in[6];
    float* out = (float*)d_out;

    const int nIng = in_sizes[0] / HIDDEN;
    const int nCmp = in_sizes[1] / HIDDEN;
    const int E    = in_sizes[2] / 2;

    const int ingBlocks = (nIng + 127) / 128;
    const int cmpBlocks = (nCmp + 127) / 128;

    const int smemBytes = HIDDEN * WS * (int)sizeof(__nv_bfloat16);  // 18.4 KB
    cudaFuncSetAttribute(precompute_mma_kernel,
                         cudaFuncAttributeMaxDynamicSharedMemorySize, smemBytes);

    precompute_mma_kernel<<<2 * (ingBlocks + cmpBlocks), 256, smemBytes>>>(
        xi, xc, W1, b1, nIng, nCmp, ingBlocks);

    edge_kernel<<<1184, 256>>>(ei, W2, b2, out, E);
}